// round 1
// baseline (speedup 1.0000x reference)
#include <cuda_runtime.h>
#include <cstdint>

#define NF          12
#define NCOMB       781          // C(12,2)+C(12,3)+C(12,4) = 66+220+495
#define NCOLS       793          // 12 + 781
#define RPB         8            // rows per block

// ---------------------------------------------------------------------------
// Compile-time combination table. Entry packs up to 4 feature indices into
// 4 bytes (lexicographic order, matching itertools.combinations). Unused
// slots hold sentinel index 12, which maps to s[12..15] = 1.0f padding.
// ---------------------------------------------------------------------------
struct Tbl { uint32_t v[NCOMB]; };

constexpr Tbl make_tbl() {
    Tbl t{};
    int p = 0;
    for (int size = 2; size <= 4; ++size) {
        int c[4] = {0, 1, 2, 3};
        for (int j = 0; j < size; ++j) c[j] = j;
        while (true) {
            uint32_t w = 0;
            for (int j = 0; j < 4; ++j) {
                uint32_t b = (j < size) ? (uint32_t)c[j] : 12u;
                w |= b << (8 * j);
            }
            t.v[p++] = w;
            // next lexicographic combination of {0..11} choose size
            int j = size - 1;
            while (j >= 0 && c[j] == NF - size + j) --j;
            if (j < 0) break;
            ++c[j];
            for (int k = j + 1; k < size; ++k) c[k] = c[k - 1] + 1;
        }
    }
    return t;
}

__device__ const Tbl d_tbl = make_tbl();

// ---------------------------------------------------------------------------
// One block = 8 rows. blockDim = (32, 8): each warp owns one row and sweeps
// its 793 output columns in coalesced 128B chunks.
// ---------------------------------------------------------------------------
__global__ __launch_bounds__(256, 8)
void schweizer_kernel(const float* __restrict__ x,
                      const float* __restrict__ lam_p,
                      float* __restrict__ out)
{
    __shared__ float s_sh[RPB][16];

    const float lam = __ldg(lam_p);
    const float inv = 1.0f / lam;

    const int tid  = threadIdx.y * 32 + threadIdx.x;
    const int row0 = blockIdx.x * RPB;

    // stage s_i = 1 - (1 - x_i)^lam for 8 rows (96 values), coalesced load
    if (tid < RPB * NF) {
        const int r = tid / NF;
        const int f = tid % NF;
        const float xv = x[(row0 + r) * NF + f];
        s_sh[r][f] = 1.0f - __powf(1.0f - xv, lam);
    }
    // sentinel padding s[12..15] = 1.0 (neutral under product)
    if (tid >= 96 && tid < 96 + RPB * 4) {
        const int t2 = tid - 96;
        s_sh[t2 / 4][12 + (t2 % 4)] = 1.0f;
    }
    __syncthreads();

    const int   r    = threadIdx.y;
    const int   row  = row0 + r;
    float*      orow = out + (size_t)row * NCOLS;
    const float* srow = s_sh[r];
    const float* xrow = x + (size_t)row * NF;

    for (int c = threadIdx.x; c < NCOLS; c += 32) {
        float v;
        if (c < NF) {
            v = xrow[c];
        } else {
            const uint32_t w = d_tbl.v[c - NF];
            const float p = srow[ w        & 15u]
                          * srow[(w >>  8) & 15u]
                          * srow[(w >> 16) & 15u]
                          * srow[(w >> 24) & 15u];
            v = 1.0f - __powf(1.0f - p, inv);
        }
        orow[c] = v;
    }
}

extern "C" void kernel_launch(void* const* d_in, const int* in_sizes, int n_in,
                              void* d_out, int out_size)
{
    const float* x   = (const float*)d_in[0];
    const float* lam = (const float*)d_in[1];
    float*       out = (float*)d_out;

    const int nrows  = in_sizes[0] / NF;   // 32768
    const int blocks = (nrows + RPB - 1) / RPB;

    dim3 bdim(32, RPB, 1);
    schweizer_kernel<<<blocks, bdim>>>(x, lam, out);
}